// round 6
// baseline (speedup 1.0000x reference)
#include <cuda_runtime.h>
#include <cuda_fp16.h>
#include <cuda.h>
#include <stdint.h>

#define TOKENS 8192
#define DIN    4096
#define DOUT   4096
#define RANK   256

// W-builder kernel staging (128x128 tile geometry)
#define W_STAGES   3
#define W_STG      (256 * 128)
#define W_SMEM     (2048 + W_STAGES * W_STG)

// main kernel staging (256x128 tile geometry)
#define M_STAGES   3
#define M_STG      (384 * 128)                 // 256 A rows + 128 B rows, 128B each
#define M_SMEM     (2048 + M_STAGES * M_STG)   // ~149.5 KB -> 1 CTA/SM

// ---------------- scratch (static device globals: allocation-free) ----------------
__device__ __half g_xh[(size_t)TOKENS * DIN];   // x in fp16
__device__ __half g_wh[(size_t)DOUT * DIN];     // W = deq(Q) + deq(L) @ deq(R), fp16
__device__ __half g_lh[(size_t)DOUT * RANK];    // dequantized L  [out, rank]
__device__ __half g_rt[(size_t)DIN * RANK];     // dequantized R^T [in, rank]

// ---------------- small conversion kernels ----------------
__global__ void cvt_x_kernel(const float* __restrict__ x) {
    int i = blockIdx.x * blockDim.x + threadIdx.x;
    float4 v = reinterpret_cast<const float4*>(x)[i];
    __half2* o = reinterpret_cast<__half2*>(g_xh);
    o[2 * i]     = __floats2half2_rn(v.x, v.y);
    o[2 * i + 1] = __floats2half2_rn(v.z, v.w);
}

__global__ void deq_kernel(const int* __restrict__ v, const float* __restrict__ s,
                           __half* __restrict__ o, int cols_log2) {
    int i = blockIdx.x * blockDim.x + threadIdx.x;
    int4 q = reinterpret_cast<const int4*>(v)[i];
    int e = i << 2;
    int r = e >> cols_log2;
    int c = e & ((1 << cols_log2) - 1);
    float sc = s[(r << (cols_log2 - 7)) + (c >> 7)];
    __half2* po = reinterpret_cast<__half2*>(o);
    po[2 * i]     = __floats2half2_rn(q.x * sc, q.y * sc);
    po[2 * i + 1] = __floats2half2_rn(q.z * sc, q.w * sc);
}

// dequantize R [RANK, DIN] -> R^T [DIN, RANK] via smem 64x64 tiles
__global__ void deq_rt_kernel(const int* __restrict__ rv, const float* __restrict__ rs) {
    __shared__ __half t[64][65];
    const int bi = blockIdx.x * 64;
    const int br = blockIdx.y * 64;
    const int tid = threadIdx.x;
    #pragma unroll
    for (int j = 0; j < 16; j++) {
        int idx = tid + j * 256;
        int rl = idx >> 6;
        int il = idx & 63;
        int r = br + rl, i = bi + il;
        float sc = rs[r * (DIN / 128) + (i >> 7)];
        t[il][rl] = __float2half_rn(rv[(size_t)r * DIN + i] * sc);
    }
    __syncthreads();
    #pragma unroll
    for (int j = 0; j < 16; j++) {
        int idx = tid + j * 256;
        int il = idx >> 6;
        int rl = idx & 63;
        g_rt[(size_t)(bi + il) * RANK + br + rl] = t[il][rl];
    }
}

// ---------------- PTX helpers ----------------
__device__ __forceinline__ uint32_t smem_u32(const void* p) {
    uint32_t a;
    asm("{ .reg .u64 t; cvta.to.shared.u64 t, %1; cvt.u32.u64 %0, t; }" : "=r"(a) : "l"(p));
    return a;
}
#define MBARRIER_INIT(addr, cnt) \
    asm volatile("mbarrier.init.shared.b64 [%0], %1;" :: "r"(addr), "r"(cnt) : "memory")
#define MBARRIER_EXPECT_TX(addr, bytes) \
    asm volatile("mbarrier.arrive.expect_tx.shared.b64 _, [%0], %1;" \
                 :: "r"(addr), "r"(bytes) : "memory")
__device__ __forceinline__ void mbar_wait_parity(uint32_t mbar, uint32_t parity) {
    uint32_t done;
    asm volatile("{ .reg .pred p; mbarrier.try_wait.parity.acquire.cta.shared::cta.b64 p, [%1], %2;"
                 " selp.b32 %0, 1, 0, p; }" : "=r"(done) : "r"(mbar), "r"(parity) : "memory");
    if (!done) {
        asm volatile("{ .reg .pred P1; WL_%=:"
                     " mbarrier.try_wait.parity.acquire.cta.shared::cta.b64 P1, [%0], %1, 0x989680;"
                     " @P1 bra.uni WD_%=; bra.uni WL_%=; WD_%=: }"
                     :: "r"(mbar), "r"(parity) : "memory");
    }
}
#define TMA_LOAD_2D(dst, map, cx, cy, mbar) \
    asm volatile("cp.async.bulk.tensor.2d.shared::cta.global.tile.mbarrier::complete_tx::bytes " \
                 "[%0], [%1, {%2, %3}], [%4];" \
                 :: "r"(dst), "l"(map), "r"(cx), "r"(cy), "r"(mbar) : "memory")
#define FENCE_PROXY_ASYNC() asm volatile("fence.proxy.async.shared::cta;" ::: "memory")

__device__ __forceinline__ void ldsm4(uint32_t r[4], uint32_t addr) {
    asm volatile("ldmatrix.sync.aligned.m8n8.x4.shared.b16 {%0,%1,%2,%3}, [%4];\n"
                 : "=r"(r[0]), "=r"(r[1]), "=r"(r[2]), "=r"(r[3]) : "r"(addr));
}
__device__ __forceinline__ void mma16816(float c[4], const uint32_t a[4],
                                         uint32_t b0, uint32_t b1) {
    asm volatile("mma.sync.aligned.m16n8k16.row.col.f32.f16.f16.f32 "
                 "{%0,%1,%2,%3},{%4,%5,%6,%7},{%8,%9},{%0,%1,%2,%3};\n"
                 : "+f"(c[0]), "+f"(c[1]), "+f"(c[2]), "+f"(c[3])
                 : "r"(a[0]), "r"(a[1]), "r"(a[2]), "r"(a[3]), "r"(b0), "r"(b1));
}

// ------------------------------------------------------------------------------
// W-builder: 128x128 tile, 8 warps 2(M)x4(N), K=256. Epilogue: +deq(Q), fp16 out.
// ------------------------------------------------------------------------------
__global__ void __launch_bounds__(256, 2) w_gemm_kernel(
    const __grid_constant__ CUtensorMap tmA,
    const __grid_constant__ CUtensorMap tmB,
    const int* __restrict__ qv, const float* __restrict__ qs,
    __half* __restrict__ outh)
{
    constexpr int TOTAL_ITERS = RANK / 64;
    extern __shared__ char smem[];
    const uint32_t sb    = smem_u32(smem);
    const uint32_t fullb = sb;
    const uint32_t tiles = (sb + 64 + 1023) & ~1023u;

    const int tid  = threadIdx.x;
    const int lane = tid & 31;
    const int wid  = tid >> 5;
    const int wm   = wid >> 2;
    const int wn   = wid & 3;
    const int m0   = blockIdx.x * 128;
    const int n0   = blockIdx.y * 128;

    if (tid == 0) {
        #pragma unroll
        for (int s = 0; s < W_STAGES; s++) MBARRIER_INIT(fullb + 8 * s, 1);
        FENCE_PROXY_ASYNC();
    }
    __syncthreads();

    if (tid == 0) {
        #pragma unroll
        for (int p = 0; p < W_STAGES; p++) {
            if (p < TOTAL_ITERS) {
                uint32_t da = tiles + p * W_STG;
                MBARRIER_EXPECT_TX(fullb + 8 * p, W_STG);
                TMA_LOAD_2D(da, &tmA, p * 64, m0, fullb + 8 * p);
                TMA_LOAD_2D(da + 128 * 128, &tmB, p * 64, n0, fullb + 8 * p);
            }
        }
    }

    float c[4][4][4];
    #pragma unroll
    for (int i = 0; i < 4; i++)
        #pragma unroll
        for (int j = 0; j < 4; j++)
            #pragma unroll
            for (int k = 0; k < 4; k++) c[i][j][k] = 0.f;

    const int lr = lane & 15;
    const int lc = lane >> 4;

    int st = 0, ph = 0;
    for (int kt = 0; kt < TOTAL_ITERS; kt++) {
        mbar_wait_parity(fullb + 8 * st, ph);
        const uint32_t sA = tiles + st * W_STG;
        const uint32_t sB = sA + 128 * 128;
        #pragma unroll
        for (int ks = 0; ks < 4; ks++) {
            uint32_t a[4][4];
            uint32_t b[2][4];
            #pragma unroll
            for (int im = 0; im < 4; im++) {
                int row = wm * 64 + im * 16 + lr;
                int ch = (ks * 2 + lc) ^ (row & 7);
                ldsm4(a[im], sA + row * 128 + (ch << 4));
            }
            #pragma unroll
            for (int j = 0; j < 2; j++) {
                int row = wn * 32 + j * 16 + lr;
                int ch = (ks * 2 + lc) ^ (row & 7);
                ldsm4(b[j], sB + row * 128 + (ch << 4));
            }
            #pragma unroll
            for (int im = 0; im < 4; im++)
                #pragma unroll
                for (int jn = 0; jn < 4; jn++)
                    mma16816(c[im][jn], a[im], b[jn >> 1][jn & 1], b[jn >> 1][2 + (jn & 1)]);
        }
        __syncthreads();
        if (tid == 0 && kt + W_STAGES < TOTAL_ITERS) {
            int st2 = st;
            uint32_t da = tiles + st2 * W_STG;
            MBARRIER_EXPECT_TX(fullb + 8 * st2, W_STG);
            TMA_LOAD_2D(da, &tmA, (kt + W_STAGES) * 64, m0, fullb + 8 * st2);
            TMA_LOAD_2D(da + 128 * 128, &tmB, (kt + W_STAGES) * 64, n0, fullb + 8 * st2);
        }
        if (++st == W_STAGES) { st = 0; ph ^= 1; }
    }

    // epilogue: W = acc + deq(Q)
    #pragma unroll
    for (int im = 0; im < 4; im++) {
        #pragma unroll
        for (int jn = 0; jn < 4; jn++) {
            int row = m0 + wm * 64 + im * 16 + (lane >> 2);
            int col = n0 + wn * 32 + jn * 8 + (lane & 3) * 2;
            #pragma unroll
            for (int h = 0; h < 2; h++) {
                int r = row + 8 * h;
                int2 q = *reinterpret_cast<const int2*>(&qv[(size_t)r * DIN + col]);
                float sc = qs[r * (DIN / 128) + (col >> 7)];
                __half2 v = __floats2half2_rn(c[im][jn][2 * h]     + q.x * sc,
                                              c[im][jn][2 * h + 1] + q.y * sc);
                *reinterpret_cast<__half2*>(&outh[(size_t)r * DIN + col]) = v;
            }
        }
    }
}

// ------------------------------------------------------------------------------
// Main GEMM: out = x @ W^T + bias. CTA tile 256x128, BK=64.
// 8 warps as 4(M) x 2(N), warp tile 64x64 -> smem reads 128KB per 1024 HMMA.
// 1 CTA/SM, 3-stage TMA pipeline, one __syncthreads per iter.
// ------------------------------------------------------------------------------
__global__ void __launch_bounds__(256, 1) main_gemm_kernel(
    const __grid_constant__ CUtensorMap tmA,      // x, box 64x256
    const __grid_constant__ CUtensorMap tmB,      // W, box 64x128
    const float* __restrict__ bias,
    float* __restrict__ outf)
{
    constexpr int TOTAL_ITERS = DIN / 64;
    extern __shared__ char smem[];
    const uint32_t sb    = smem_u32(smem);
    const uint32_t fullb = sb;
    const uint32_t tiles = (sb + 64 + 1023) & ~1023u;

    const int tid  = threadIdx.x;
    const int lane = tid & 31;
    const int wid  = tid >> 5;
    const int wm   = wid >> 1;      // 0..3 (M)
    const int wn   = wid & 1;       // 0..1 (N)
    const int m0   = blockIdx.x * 256;
    const int n0   = blockIdx.y * 128;

    if (tid == 0) {
        #pragma unroll
        for (int s = 0; s < M_STAGES; s++) MBARRIER_INIT(fullb + 8 * s, 1);
        FENCE_PROXY_ASYNC();
    }
    __syncthreads();

    auto issue = [&](int kt, int st) {
        uint32_t da = tiles + st * M_STG;
        MBARRIER_EXPECT_TX(fullb + 8 * st, M_STG);
        TMA_LOAD_2D(da, &tmA, kt * 64, m0, fullb + 8 * st);                 // 32KB A
        TMA_LOAD_2D(da + 256 * 128, &tmB, kt * 64, n0, fullb + 8 * st);     // 16KB B
    };

    if (tid == 0) {
        #pragma unroll
        for (int p = 0; p < M_STAGES; p++) issue(p, p);
    }

    float c[4][8][4];
    #pragma unroll
    for (int i = 0; i < 4; i++)
        #pragma unroll
        for (int j = 0; j < 8; j++)
            #pragma unroll
            for (int k = 0; k < 4; k++) c[i][j][k] = 0.f;

    const int lr = lane & 15;
    const int lc = lane >> 4;

    int st = 0, ph = 0;
    for (int kt = 0; kt < TOTAL_ITERS; kt++) {
        mbar_wait_parity(fullb + 8 * st, ph);

        const uint32_t sA = tiles + st * M_STG;
        const uint32_t sB = sA + 256 * 128;

        #pragma unroll
        for (int ks = 0; ks < 4; ks++) {
            uint32_t a[4][4];
            uint32_t b[4][4];
            #pragma unroll
            for (int im = 0; im < 4; im++) {
                int row = wm * 64 + im * 16 + lr;
                int ch = (ks * 2 + lc) ^ (row & 7);
                ldsm4(a[im], sA + row * 128 + (ch << 4));
            }
            #pragma unroll
            for (int j = 0; j < 4; j++) {
                int row = wn * 64 + j * 16 + lr;
                int ch = (ks * 2 + lc) ^ (row & 7);
                ldsm4(b[j], sB + row * 128 + (ch << 4));
            }
            #pragma unroll
            for (int im = 0; im < 4; im++) {
                #pragma unroll
                for (int jn = 0; jn < 8; jn++) {
                    mma16816(c[im][jn], a[im], b[jn >> 1][jn & 1], b[jn >> 1][2 + (jn & 1)]);
                }
            }
        }

        __syncthreads();
        if (tid == 0 && kt + M_STAGES < TOTAL_ITERS) issue(kt + M_STAGES, st);

        if (++st == M_STAGES) { st = 0; ph ^= 1; }
    }

    // ---- epilogue: + bias, fp32 out ----
    #pragma unroll
    for (int im = 0; im < 4; im++) {
        #pragma unroll
        for (int jn = 0; jn < 8; jn++) {
            int row = m0 + wm * 64 + im * 16 + (lane >> 2);
            int col = n0 + wn * 64 + jn * 8 + (lane & 3) * 2;
            float b0 = bias[col];
            float b1 = bias[col + 1];
            float2 v0 = make_float2(c[im][jn][0] + b0, c[im][jn][1] + b1);
            float2 v1 = make_float2(c[im][jn][2] + b0, c[im][jn][3] + b1);
            *reinterpret_cast<float2*>(outf + (size_t)row * DOUT + col) = v0;
            *reinterpret_cast<float2*>(outf + (size_t)(row + 8) * DOUT + col) = v1;
        }
    }
}

// ---------------- host: tensor maps + launch ----------------
typedef CUresult (*EncodeTiledFn)(
    CUtensorMap*, CUtensorMapDataType, cuuint32_t, void*,
    const cuuint64_t*, const cuuint64_t*, const cuuint32_t*, const cuuint32_t*,
    CUtensorMapInterleave, CUtensorMapSwizzle, CUtensorMapL2promotion,
    CUtensorMapFloatOOBfill);

static void make_map_f16(EncodeTiledFn enc, CUtensorMap* tm, void* base,
                         uint64_t dim0, uint64_t dim1, uint64_t pitch_bytes,
                         uint32_t box1) {
    uint64_t dims[2] = {dim0, dim1};
    uint64_t strides[1] = {pitch_bytes};
    uint32_t box[2] = {64, box1};
    uint32_t es[2] = {1, 1};
    enc(tm, CU_TENSOR_MAP_DATA_TYPE_FLOAT16, 2, base, dims, strides, box, es,
        CU_TENSOR_MAP_INTERLEAVE_NONE, CU_TENSOR_MAP_SWIZZLE_128B,
        CU_TENSOR_MAP_L2_PROMOTION_L2_128B, CU_TENSOR_MAP_FLOAT_OOB_FILL_NONE);
}

extern "C" void kernel_launch(void* const* d_in, const int* in_sizes, int n_in,
                              void* d_out, int out_size) {
    const float* x    = (const float*)d_in[0];
    const int*   qv   = (const int*)  d_in[1];
    const float* qs   = (const float*)d_in[2];
    const int*   lv   = (const int*)  d_in[3];
    const float* ls   = (const float*)d_in[4];
    const int*   rv   = (const int*)  d_in[5];
    const float* rs   = (const float*)d_in[6];
    const float* bias = (const float*)d_in[7];
    float* out = (float*)d_out;

    __half *pxh, *pwh, *plh, *prt;
    cudaGetSymbolAddress((void**)&pxh, g_xh);
    cudaGetSymbolAddress((void**)&pwh, g_wh);
    cudaGetSymbolAddress((void**)&plh, g_lh);
    cudaGetSymbolAddress((void**)&prt, g_rt);

    EncodeTiledFn enc = nullptr;
    {
        void* fp = nullptr;
        cudaDriverEntryPointQueryResult st;
        cudaGetDriverEntryPointByVersion("cuTensorMapEncodeTiled", &fp, 12000,
                                         cudaEnableDefault, &st);
        enc = (EncodeTiledFn)fp;
    }

    CUtensorMap tmX, tmW, tmL, tmRT;
    make_map_f16(enc, &tmX,  pxh, DIN,  TOKENS, (uint64_t)DIN * 2,  256);  // A, box 64x256
    make_map_f16(enc, &tmW,  pwh, DIN,  DOUT,   (uint64_t)DIN * 2,  128);  // B, box 64x128
    make_map_f16(enc, &tmL,  plh, RANK, DOUT,   (uint64_t)RANK * 2, 128);
    make_map_f16(enc, &tmRT, prt, RANK, DIN,    (uint64_t)RANK * 2, 128);

    cudaFuncSetAttribute(w_gemm_kernel,    cudaFuncAttributeMaxDynamicSharedMemorySize, W_SMEM);
    cudaFuncSetAttribute(main_gemm_kernel, cudaFuncAttributeMaxDynamicSharedMemorySize, M_SMEM);

    // pre-pass
    cvt_x_kernel<<<(TOKENS * DIN / 4) / 256, 256>>>(x);
    deq_kernel<<<((size_t)DOUT * RANK / 4) / 256, 256>>>(lv, ls, plh, 8);   // L
    deq_rt_kernel<<<dim3(DIN / 64, RANK / 64), 256>>>(rv, rs);              // R^T

    // W = deq(L) @ deq(R)^T + deq(Q)
    w_gemm_kernel<<<dim3(DOUT / 128, DIN / 128), 256, W_SMEM>>>(tmL, tmRT, qv, qs, pwh);

    // out = x @ W^T + bias
    main_gemm_kernel<<<dim3(TOKENS / 256, DOUT / 128), 256, M_SMEM>>>(tmX, tmW, bias, out);
}